// round 13
// baseline (speedup 1.0000x reference)
#include <cuda_runtime.h>
#include <math.h>

#define TT 5
#define ZZ 32
#define YY 512
#define XX 512
#define N_RAYS 10000
#define N_STEPS 768
#define VOXEL 0.2f
#define BREAK_S 11.0f      // tail <= e^-11 * 768 * 0.2 ~ 2.6e-3 m: << budget
#define BATCH 16           // steps per ray per iteration (4 per quad lane)
#define N_BATCH (N_STEPS / BATCH)   // 48

// Cross-launch-safe accumulators: zero at module load; last block resets them
// at the end of every launch, so each graph replay sees zeros.
__device__ float g_acc[3] = {0.0f, 0.0f, 0.0f};
__device__ unsigned int g_count = 0u;

__global__ void __launch_bounds__(32)
ray_march_loss_kernel(const float* __restrict__ grid,
                      const float* __restrict__ origin,   // [T,3]
                      const float* __restrict__ points,   // [N_RAYS,3]
                      const int*   __restrict__ tindex,   // [N_RAYS]
                      float* __restrict__ out)            // [3]
{
    const unsigned FULL = 0xffffffffu;
    int lane = threadIdx.x;                  // 0..31
    int sub  = lane & 3;                     // sub-lane within quad
    int ray  = blockIdx.x * 8 + (lane >> 2); // 4 lanes per ray, 8 rays/warp
    // 1250 blocks * 8 rays = 10000 exactly

    const float offx = -51.2f, offy = -51.2f, offz = -3.2f;
    const float inv_vox = 5.0f;

    // --- Independent loads issued up front, all in parallel:
    int ti = tindex[ray];
    float px = (points[ray * 3 + 0] - offx) * inv_vox;
    float py = (points[ray * 3 + 1] - offy) * inv_vox;
    float pz = (points[ray * 3 + 2] - offz) * inv_vox;

    // All 5 origins (uniform addresses) — no dependency on ti:
    float og[15];
    #pragma unroll
    for (int i = 0; i < 15; ++i) og[i] = origin[i];

    float ox = og[0], oy = og[1], oz = og[2];
    #pragma unroll
    for (int tt = 1; tt < TT; ++tt) {
        if (ti == tt) { ox = og[3*tt]; oy = og[3*tt+1]; oz = og[3*tt+2]; }
    }
    ox = (ox - offx) * inv_vox;
    oy = (oy - offy) * inv_vox;
    oz = (oz - offz) * inv_vox;

    float dx = px - ox, dy = py - oy, dz = pz - oz;
    float d2 = fmaxf(dx * dx + dy * dy + dz * dz, 1e-12f);
    float rinv = rsqrtf(d2);                 // = 1/|dirv|
    float gt = d2 * rinv;                    // = |dirv|
    float ux = dx * rinv, uy = dy * rinv, uz = dz * rinv;

    const float* base = grid + ((size_t)ti << 23);   // ti * 32*512*512

    // === Issue batch-0 gathers IMMEDIATELY; clip math overlaps the loads ===
    float tau[4];
    {
        int k0 = sub * 4;
        #pragma unroll
        for (int j = 0; j < 4; ++j) {
            float t = (float)(k0 + j) + 0.5f;
            float fx = ox + ux * t;
            float fy = oy + uy * t;
            float fz = oz + uz * t;
            int ix = __float2int_rd(fx);
            int iy = __float2int_rd(fy);
            int iz = __float2int_rd(fz);
            bool inb = ((unsigned)ix < XX) & ((unsigned)iy < YY) &
                       ((unsigned)iz < ZZ);
            float v = 0.0f;
            if (inb) v = __ldg(base + (((iz << 9) + iy) << 9) + ix);
            tau[j] = fmaxf(v, 0.0f);
        }
    }

    // Exit-only clip (origin inside box; per-sample bounds guard keeps
    // exactness regardless — this is purely a work bound).
    float tex = (fabsf(ux) > 1e-8f)
              ? __fdividef((ux > 0.0f ? (float)XX : 0.0f) - ox, ux) : 1e9f;
    float tey = (fabsf(uy) > 1e-8f)
              ? __fdividef((uy > 0.0f ? (float)YY : 0.0f) - oy, uy) : 1e9f;
    float tez = (fabsf(uz) > 1e-8f)
              ? __fdividef((uz > 0.0f ? (float)ZZ : 0.0f) - oz, uz) : 1e9f;
    float te = fminf(tex, fminf(tey, tez));
    if (te < 0.0f) te = (float)N_STEPS;      // degenerate: full march
    int k_exit = min(N_STEPS - 1, (int)te + 1);

    float pred = 0.0f;
    float S = 0.0f;
    bool alive = true;

    #pragma unroll 1
    for (int b = 0; ; ) {
        int   k0 = b * BATCH + sub * 4;
        float tf = (float)k0 + 0.5f;

        // Lane-local prefix (3 serial FADDs)
        float c1 = tau[0];
        float c2 = c1 + tau[1];
        float c3 = c2 + tau[2];
        float lsum = c3 + tau[3];

        // 2-level inclusive scan across the quad
        float sc = lsum;
        float v1 = __shfl_up_sync(FULL, sc, 1, 4); if (sub >= 1) sc += v1;
        float v2 = __shfl_up_sync(FULL, sc, 2, 4); if (sub >= 2) sc += v2;
        float tot  = __shfl_sync(FULL, sc, 3, 4);
        float excl = sc - lsum;

        // 5 INDEPENDENT exponentials (pipeline through MUFU)
        float s0 = S + excl;
        float e0 = __expf(-s0);
        float e1 = __expf(-(s0 + c1));
        float e2 = __expf(-(s0 + c2));
        float e3 = __expf(-(s0 + c3));
        float e4 = __expf(-(s0 + lsum));

        if (alive) {
            pred += (e0 - e1) * tf
                  + (e1 - e2) * (tf + 1.0f)
                  + (e2 - e3) * (tf + 2.0f)
                  + (e3 - e4) * (tf + 3.0f);
        }

        S += tot;
        alive = alive && (S <= BREAK_S) && ((b + 1) * BATCH <= k_exit);
        ++b;
        if (b >= N_BATCH || !__ballot_sync(FULL, alive)) break;

        // Fetch next batch (only reached if some ray in warp is alive)
        int kn = b * BATCH + sub * 4;
        #pragma unroll
        for (int j = 0; j < 4; ++j) {
            float t = (float)(kn + j) + 0.5f;
            float fx = ox + ux * t;
            float fy = oy + uy * t;
            float fz = oz + uz * t;
            int ix = __float2int_rd(fx);
            int iy = __float2int_rd(fy);
            int iz = __float2int_rd(fz);
            bool inb = alive &
                       ((unsigned)ix < XX) & ((unsigned)iy < YY) &
                       ((unsigned)iz < ZZ);
            float v = 0.0f;
            if (inb) v = __ldg(base + (((iz << 9) + iy) << 9) + ix);
            tau[j] = fmaxf(v, 0.0f);
        }
    }

    // Combine quad partials of pred
    pred += __shfl_xor_sync(FULL, pred, 1, 4);
    pred += __shfl_xor_sync(FULL, pred, 2, 4);

    // Per-ray loss on quad leader only
    float l1 = 0.0f, l2 = 0.0f, l3 = 0.0f;
    if (sub == 0) {
        float p = pred * VOXEL;
        float g = gt * VOXEL;
        float d = g - p;
        float ad = fabsf(d);
        l1 = ad;
        l2 = 0.5f * d * d;
        l3 = ad / fmaxf(g, 1e-6f);
    }

    // Warp reduce across the 8 rays
    #pragma unroll
    for (int o = 16; o > 0; o >>= 1) {
        l1 += __shfl_xor_sync(FULL, l1, o);
        l2 += __shfl_xor_sync(FULL, l2, o);
        l3 += __shfl_xor_sync(FULL, l3, o);
    }

    if (lane == 0) {
        atomicAdd(&g_acc[0], l1);
        atomicAdd(&g_acc[1], l2);
        atomicAdd(&g_acc[2], l3);
        __threadfence();
        unsigned int prev = atomicAdd(&g_count, 1u);
        if (prev == gridDim.x - 1) {
            // Last block: publish result and reset for next replay
            const float inv_count = 1.0f / (float)N_RAYS;
            volatile float* acc = g_acc;
            float a = acc[0], b2 = acc[1], c2 = acc[2];
            out[0] = a  * inv_count;
            out[1] = b2 * inv_count;
            out[2] = c2 * inv_count;
            g_acc[0] = 0.0f; g_acc[1] = 0.0f; g_acc[2] = 0.0f;
            g_count = 0u;
            __threadfence();
        }
    }
}

extern "C" void kernel_launch(void* const* d_in, const int* in_sizes, int n_in,
                              void* d_out, int out_size)
{
    const float* grid    = (const float*)d_in[0];  // [1,5,32,512,512]
    const float* origin  = (const float*)d_in[1];  // [1,5,3]
    const float* points  = (const float*)d_in[2];  // [1,10000,3]
    const int*   tindex  = (const int*)d_in[3];    // [1,10000]
    float* out = (float*)d_out;

    // 8 rays per single-warp block (4 lanes per ray); 1250 blocks = 10000 rays
    ray_march_loss_kernel<<<1250, 32>>>(grid, origin, points, tindex, out);
}

// round 14
// speedup vs baseline: 1.3528x; 1.3528x over previous
#include <cuda_runtime.h>
#include <math.h>

#define TT 5
#define ZZ 32
#define YY 512
#define XX 512
#define N_RAYS 10000
#define N_STEPS 768
#define VOXEL 0.2f
#define BREAK_S 11.0f      // tail <= e^-11 * 768 * 0.2 ~ 2.6e-3 m: << budget
#define BATCH 16           // steps per ray per iteration (4 per sub-lane)
#define N_BATCH (N_STEPS / BATCH)   // 48

// Cross-launch-safe accumulators: zero at module load; last block resets them
// at the end of every launch, so each graph replay sees zeros.
__device__ float g_acc[3] = {0.0f, 0.0f, 0.0f};
__device__ unsigned int g_count = 0u;

__global__ void __launch_bounds__(128)
ray_march_loss_kernel(const float* __restrict__ grid,
                      const float* __restrict__ origin,   // [T,3]
                      const float* __restrict__ points,   // [N_RAYS,3]
                      const int*   __restrict__ tindex,   // [N_RAYS]
                      float* __restrict__ out)            // [3]
{
    const unsigned FULL = 0xffffffffu;
    int lane = threadIdx.x & 31;
    int wid  = threadIdx.x >> 5;            // warp in block (0..3)
    int sub  = lane & 3;                    // sub-lane within quad
    int ray  = blockIdx.x * 32 + (threadIdx.x >> 2);   // 4 threads per ray
    bool have_ray = (ray < N_RAYS);

    __shared__ float s1[4], s2[4], s3[4];
    __shared__ bool  s_last;

    float gt = 0.0f, pred = 0.0f;

    float ox = 0, oy = 0, oz = 0, ux = 0, uy = 0, uz = 0;
    const float* base = grid;
    int k_exit = 0;

    if (have_ray) {
        const float offx = -51.2f, offy = -51.2f, offz = -3.2f;
        const float inv_vox = 5.0f;

        // Independent loads issued up front, all in parallel:
        int ti = tindex[ray];
        float px = (points[ray * 3 + 0] - offx) * inv_vox;
        float py = (points[ray * 3 + 1] - offy) * inv_vox;
        float pz = (points[ray * 3 + 2] - offz) * inv_vox;

        // All 5 origins (uniform addresses) — no dependency on ti:
        float og[15];
        #pragma unroll
        for (int i = 0; i < 15; ++i) og[i] = origin[i];

        ox = og[0]; oy = og[1]; oz = og[2];
        #pragma unroll
        for (int tt = 1; tt < TT; ++tt) {
            if (ti == tt) { ox = og[3*tt]; oy = og[3*tt+1]; oz = og[3*tt+2]; }
        }
        ox = (ox - offx) * inv_vox;
        oy = (oy - offy) * inv_vox;
        oz = (oz - offz) * inv_vox;

        float dx = px - ox, dy = py - oy, dz = pz - oz;
        float d2 = fmaxf(dx * dx + dy * dy + dz * dz, 1e-12f);
        float rinv = rsqrtf(d2);              // = 1/|dirv|
        gt = d2 * rinv;                       // = |dirv|
        ux = dx * rinv; uy = dy * rinv; uz = dz * rinv;

        base = grid + ((size_t)ti << 23);     // ti * 32*512*512

        // Exit-only clip (origin inside box; per-sample bounds guard keeps
        // exactness regardless — this is purely a work bound).
        float tex = (fabsf(ux) > 1e-8f)
                  ? __fdividef((ux > 0.0f ? (float)XX : 0.0f) - ox, ux) : 1e9f;
        float tey = (fabsf(uy) > 1e-8f)
                  ? __fdividef((uy > 0.0f ? (float)YY : 0.0f) - oy, uy) : 1e9f;
        float tez = (fabsf(uz) > 1e-8f)
                  ? __fdividef((uz > 0.0f ? (float)ZZ : 0.0f) - oz, uz) : 1e9f;
        float te = fminf(tex, fminf(tey, tez));
        if (te < 0.0f) te = (float)N_STEPS;   // degenerate: full march
        k_exit = min(N_STEPS - 1, (int)te + 1);
    }

    float S = 0.0f;                           // cumulative tau (quad-uniform)
    bool alive = have_ray;

    #pragma unroll 1
    for (int b = 0; b < N_BATCH; ++b) {
        if (!__ballot_sync(FULL, alive)) break;

        int k0 = b * BATCH + sub * 4;         // this sub-lane's 4 steps
        float tf = (float)k0 + 0.5f;

        // 4 independent gathers
        float tau[4];
        #pragma unroll
        for (int j = 0; j < 4; ++j) {
            float t = tf + (float)j;
            float fx = ox + ux * t;
            float fy = oy + uy * t;
            float fz = oz + uz * t;
            int ix = __float2int_rd(fx);
            int iy = __float2int_rd(fy);
            int iz = __float2int_rd(fz);
            bool inb = alive &
                       ((unsigned)ix < XX) & ((unsigned)iy < YY) &
                       ((unsigned)iz < ZZ);
            float v = 0.0f;
            if (inb)
                v = __ldg(base + (((iz << 9) + iy) << 9) + ix);
            tau[j] = fmaxf(v, 0.0f);
        }

        // Lane-local prefix (3 serial FADDs)
        float c1 = tau[0];
        float c2 = c1 + tau[1];
        float c3 = c2 + tau[2];
        float lsum = c3 + tau[3];

        // 2-level inclusive scan across the quad
        float sc = lsum;
        float v1 = __shfl_up_sync(FULL, sc, 1, 4); if (sub >= 1) sc += v1;
        float v2 = __shfl_up_sync(FULL, sc, 2, 4); if (sub >= 2) sc += v2;
        float tot  = __shfl_sync(FULL, sc, 3, 4);
        float excl = sc - lsum;

        // 5 INDEPENDENT exponentials (pipeline through MUFU, no serial chain)
        float s0 = S + excl;
        float e0 = __expf(-s0);
        float e1 = __expf(-(s0 + c1));
        float e2 = __expf(-(s0 + c2));
        float e3 = __expf(-(s0 + c3));
        float e4 = __expf(-(s0 + lsum));

        pred += (e0 - e1) * tf
              + (e1 - e2) * (tf + 1.0f)
              + (e2 - e3) * (tf + 2.0f)
              + (e3 - e4) * (tf + 3.0f);

        S += tot;
        alive = alive && (S <= BREAK_S) && ((b + 1) * BATCH <= k_exit);
    }

    // Combine quad partials of pred
    pred += __shfl_xor_sync(FULL, pred, 1, 4);
    pred += __shfl_xor_sync(FULL, pred, 2, 4);

    // Per-ray loss on sub-lane 0 only
    float l1 = 0.0f, l2 = 0.0f, l3 = 0.0f;
    if (have_ray && sub == 0) {
        float p = pred * VOXEL;
        float g = gt * VOXEL;
        float d = g - p;
        float ad = fabsf(d);
        l1 = ad;
        l2 = 0.5f * d * d;
        l3 = ad / fmaxf(g, 1e-6f);
    }

    // Warp reduce
    #pragma unroll
    for (int o = 16; o > 0; o >>= 1) {
        l1 += __shfl_xor_sync(FULL, l1, o);
        l2 += __shfl_xor_sync(FULL, l2, o);
        l3 += __shfl_xor_sync(FULL, l3, o);
    }

    if (lane == 0) {
        s1[wid] = l1; s2[wid] = l2; s3[wid] = l3;
    }
    __syncthreads();
    if (threadIdx.x == 0) {
        float a = 0.0f, b2 = 0.0f, c2 = 0.0f;
        #pragma unroll
        for (int i = 0; i < 4; ++i) { a += s1[i]; b2 += s2[i]; c2 += s3[i]; }
        atomicAdd(&g_acc[0], a);
        atomicAdd(&g_acc[1], b2);
        atomicAdd(&g_acc[2], c2);
        __threadfence();
        unsigned int prev = atomicAdd(&g_count, 1u);
        s_last = (prev == gridDim.x - 1);
    }
    __syncthreads();

    // Last block: publish result and reset accumulators for next replay
    if (s_last && threadIdx.x == 0) {
        const float inv_count = 1.0f / (float)N_RAYS;
        volatile float* acc = g_acc;
        float a = acc[0], b2 = acc[1], c2 = acc[2];
        out[0] = a  * inv_count;
        out[1] = b2 * inv_count;
        out[2] = c2 * inv_count;
        g_acc[0] = 0.0f; g_acc[1] = 0.0f; g_acc[2] = 0.0f;
        g_count = 0u;
        __threadfence();
    }
}

extern "C" void kernel_launch(void* const* d_in, const int* in_sizes, int n_in,
                              void* d_out, int out_size)
{
    const float* grid    = (const float*)d_in[0];  // [1,5,32,512,512]
    const float* origin  = (const float*)d_in[1];  // [1,5,3]
    const float* points  = (const float*)d_in[2];  // [1,10000,3]
    const int*   tindex  = (const int*)d_in[3];    // [1,10000]
    float* out = (float*)d_out;

    // 32 rays per 128-thread block (4 lanes per ray); 313 blocks
    int blocks = (N_RAYS + 31) / 32;   // 313
    ray_march_loss_kernel<<<blocks, 128>>>(grid, origin, points, tindex, out);
}